// round 1
// baseline (speedup 1.0000x reference)
#include <cuda_runtime.h>

#define VERT   16384
#define D      256
#define DEG    128
#define S      32
#define SENT   99999
#define TILE_M 64
#define THREADS 256
#define BK     8
#define ASTR   68   // padded A-tile stride: (4*kk + m) mod 32 all-distinct -> conflict-free

// packed fp32x2 FMA (exact fp32 per half, 2x FFMA throughput on sm_103a)
__device__ __forceinline__ void fma2(unsigned long long &d, unsigned long long a,
                                     unsigned long long b) {
    asm("fma.rn.f32x2 %0, %1, %2, %0;" : "+l"(d) : "l"(a), "l"(b));
}
__device__ __forceinline__ unsigned long long pack2(float x) {
    unsigned long long r;
    asm("mov.b64 %0, {%1, %1};" : "=l"(r) : "f"(x));
    return r;
}
union F2U { unsigned long long u; float2 f; };

__global__ __launch_bounds__(THREADS, 2)
void fused_sampler_kernel(const int* __restrict__ ids,
                          const int* __restrict__ unif_rand,
                          const int* __restrict__ adj_info,
                          const float* __restrict__ features,
                          const float* __restrict__ W,
                          const float* __restrict__ bias,
                          float* __restrict__ out)
{
    extern __shared__ float smem[];
    float* ls   = smem;                      // [TILE_M][D]   64 KB
    float* As   = ls + TILE_M * D;           // [BK][ASTR]
    float* Bs   = As + BK * ASTR;            // [BK][D]
    int*   grow = (int*)(Bs + BK * D);       // [TILE_M]
    int*   ur   = grow + TILE_M;             // [S]

    const int tid = threadIdx.x;
    const int m0  = blockIdx.x * TILE_M;

    if (tid < TILE_M) grow[tid] = ids[m0 + tid];
    if (tid < S)      ur[tid]   = unif_rand[tid];
    __syncthreads();

    // ---------------- Phase A: l = features[ids_tile] @ W + b  (into SMEM) -------------
    // thread (rg, cg): rows rg*8..rg*8+7, cols {cg*4..+3, 128+cg*4..+3}
    const int rg = tid >> 5;
    const int cg = tid & 31;

    unsigned long long acc[4][8];   // acc[i2][j]: rows (2*i2, 2*i2+1) packed, col j
#pragma unroll
    for (int i = 0; i < 4; i++)
#pragma unroll
        for (int j = 0; j < 8; j++) acc[i][j] = 0ull;

    for (int k0 = 0; k0 < D; k0 += BK) {
        // load A tile (gathered rows), transposed [kk][m]
#pragma unroll
        for (int p = 0; p < 2; p++) {
            int e  = tid + p * THREADS;        // 0..511
            int kk = e & (BK - 1);
            int m  = e >> 3;
            As[kk * ASTR + m] = features[(size_t)grow[m] * D + k0 + kk];
        }
        // load B tile [kk][n]
#pragma unroll
        for (int p = 0; p < 2; p++) {
            int e  = tid + p * THREADS;        // 0..511
            int kk = e >> 6;                   // 0..7
            int n4 = (e & 63) * 4;
            *(float4*)&Bs[kk * D + n4] = *(const float4*)&W[(size_t)(k0 + kk) * D + n4];
        }
        __syncthreads();
#pragma unroll
        for (int kk = 0; kk < BK; kk++) {
            // A: 8 rows for this warp-row group, as 4 packed pairs (direct 64-bit reads)
            ulonglong2 aP0 = *(ulonglong2*)&As[kk * ASTR + rg * 8];
            ulonglong2 aP1 = *(ulonglong2*)&As[kk * ASTR + rg * 8 + 4];
            unsigned long long a_[4] = {aP0.x, aP0.y, aP1.x, aP1.y};
            float4 b0 = *(float4*)&Bs[kk * D + cg * 4];
            float4 b1 = *(float4*)&Bs[kk * D + 128 + cg * 4];
            unsigned long long bb[8];
            bb[0] = pack2(b0.x); bb[1] = pack2(b0.y); bb[2] = pack2(b0.z); bb[3] = pack2(b0.w);
            bb[4] = pack2(b1.x); bb[5] = pack2(b1.y); bb[6] = pack2(b1.z); bb[7] = pack2(b1.w);
#pragma unroll
            for (int i2 = 0; i2 < 4; i2++)
#pragma unroll
                for (int j = 0; j < 8; j++)
                    fma2(acc[i2][j], a_[i2], bb[j]);
        }
        __syncthreads();
    }

    // bias + write l tile to SMEM
    {
        float4 bias0 = *(const float4*)&bias[cg * 4];
        float4 bias1 = *(const float4*)&bias[128 + cg * 4];
        float bjs[8] = {bias0.x, bias0.y, bias0.z, bias0.w,
                        bias1.x, bias1.y, bias1.z, bias1.w};
#pragma unroll
        for (int i2 = 0; i2 < 4; i2++) {
            float lo[8], hi[8];
#pragma unroll
            for (int j = 0; j < 8; j++) {
                F2U u; u.u = acc[i2][j];
                lo[j] = u.f.x + bjs[j];
                hi[j] = u.f.y + bjs[j];
            }
            int r0 = rg * 8 + 2 * i2;
            *(float4*)&ls[r0 * D + cg * 4]        = make_float4(lo[0], lo[1], lo[2], lo[3]);
            *(float4*)&ls[r0 * D + 128 + cg * 4]  = make_float4(lo[4], lo[5], lo[6], lo[7]);
            *(float4*)&ls[(r0 + 1) * D + cg * 4]       = make_float4(hi[0], hi[1], hi[2], hi[3]);
            *(float4*)&ls[(r0 + 1) * D + 128 + cg * 4] = make_float4(hi[4], hi[5], hi[6], hi[7]);
        }
    }
    __syncthreads();

    // ---------------- Phase B: neighbor gather + dot + outputs ----------------
    const int warp = tid >> 5;
    const int lane = tid & 31;
    const int myur = ur[lane];
    const size_t attOff = (size_t)VERT * S;        // 524288
    const size_t nzOff  = (size_t)VERT * S * 2;    // 1048576
    const size_t mnOff  = nzOff + VERT;            // 1064960

    for (int t = 0; t < 8; t++) {
        const int v  = warp * 8 + t;
        const int gv = m0 + v;
        const int ga = grow[v];
        const int nb = adj_info[(size_t)ga * DEG + myur];  // lane's own sample

        float4 l0 = *(float4*)&ls[v * D + lane * 8];
        float4 l1 = *(float4*)&ls[v * D + lane * 8 + 4];

        float myout = 0.0f;
        // 1-deep pipeline over samples
        int nbs = __shfl_sync(0xffffffffu, nb, 0);
        const float4* fp = (const float4*)&features[(size_t)nbs * D];
        float4 f0 = fp[lane * 2];
        float4 f1 = fp[lane * 2 + 1];
#pragma unroll
        for (int s = 0; s < S; s++) {
            float4 c0 = f0, c1 = f1;
            if (s + 1 < S) {
                int nn = __shfl_sync(0xffffffffu, nb, s + 1);
                const float4* fq = (const float4*)&features[(size_t)nn * D];
                f0 = fq[lane * 2];
                f1 = fq[lane * 2 + 1];
            }
            float sum = c0.x * l0.x + c0.y * l0.y + c0.z * l0.z + c0.w * l0.w
                      + c1.x * l1.x + c1.y * l1.y + c1.z * l1.z + c1.w * l1.w;
#pragma unroll
            for (int off = 16; off; off >>= 1)
                sum += __shfl_xor_sync(0xffffffffu, sum, off);
            float o = fmaxf(sum, 0.0f);
            if (lane == s) myout = o;
        }

        float mean = myout;
#pragma unroll
        for (int off = 16; off; off >>= 1)
            mean += __shfl_xor_sync(0xffffffffu, mean, off);
        mean *= (1.0f / S);

        const bool cond = (nb == SENT) || (myout > 0.5f * mean);
        out[(size_t)gv * S + lane]          = (float)(cond ? SENT : nb);
        out[attOff + (size_t)gv * S + lane] = 1.0f;

        float nz = cond ? 0.0f : 1.0f;
#pragma unroll
        for (int off = 16; off; off >>= 1)
            nz += __shfl_xor_sync(0xffffffffu, nz, off);
        if (lane == 0) {
            out[nzOff + gv] = nz;
            out[mnOff + gv] = mean;
        }
    }
}

extern "C" void kernel_launch(void* const* d_in, const int* in_sizes, int n_in,
                              void* d_out, int out_size)
{
    (void)in_sizes; (void)n_in; (void)out_size;
    const int*   ids  = (const int*)d_in[0];
    const int*   urnd = (const int*)d_in[1];
    const int*   adj  = (const int*)d_in[2];
    const float* feat = (const float*)d_in[3];
    const float* W    = (const float*)d_in[4];
    const float* b    = (const float*)d_in[5];
    float*       out  = (float*)d_out;

    const size_t smem_bytes =
        (size_t)(TILE_M * D + BK * ASTR + BK * D) * sizeof(float) +
        (size_t)(TILE_M + S) * sizeof(int);    // 76288 bytes

    cudaFuncSetAttribute(fused_sampler_kernel,
                         cudaFuncAttributeMaxDynamicSharedMemorySize,
                         (int)smem_bytes);

    fused_sampler_kernel<<<VERT / TILE_M, THREADS, smem_bytes>>>(
        ids, urnd, adj, feat, W, b, out);
}

// round 2
// speedup vs baseline: 1.0220x; 1.0220x over previous
#include <cuda_runtime.h>

#define VERT   16384
#define D      256
#define DEG    128
#define S      32
#define SENT   99999
#define TILE_M 64
#define THREADS 256
#define BK     8
#define ASTR   68   // padded A-tile stride -> conflict-free transposed stores

// packed fp32x2 FMA (exact fp32 per half, 2x FFMA throughput on sm_103a)
__device__ __forceinline__ void fma2(unsigned long long &d, unsigned long long a,
                                     unsigned long long b) {
    asm("fma.rn.f32x2 %0, %1, %2, %0;" : "+l"(d) : "l"(a), "l"(b));
}
__device__ __forceinline__ unsigned long long pack2(float x) {
    unsigned long long r;
    asm("mov.b64 %0, {%1, %1};" : "=l"(r) : "f"(x));
    return r;
}
union F2U { unsigned long long u; float2 f; };

__global__ __launch_bounds__(THREADS, 2)
void fused_sampler_kernel(const int* __restrict__ ids,
                          const int* __restrict__ unif_rand,
                          const int* __restrict__ adj_info,
                          const float* __restrict__ features,
                          const float* __restrict__ W,
                          const float* __restrict__ bias,
                          float* __restrict__ out)
{
    extern __shared__ float smem[];
    float* ls   = smem;                      // [TILE_M][D]   64 KB
    float* As   = ls + TILE_M * D;           // [BK][ASTR]
    float* Bs   = As + BK * ASTR;            // [BK][D]
    int*   grow = (int*)(Bs + BK * D);       // [TILE_M]
    int*   ur   = grow + TILE_M;             // [S]

    const int tid = threadIdx.x;
    const int m0  = blockIdx.x * TILE_M;

    if (tid < TILE_M) grow[tid] = ids[m0 + tid];
    if (tid < S)      ur[tid]   = unif_rand[tid];
    __syncthreads();

    // ---------------- Phase A: l = features[ids_tile] @ W + b  (into SMEM) -------------
    const int rg = tid >> 5;
    const int cg = tid & 31;

    unsigned long long acc[4][8];
#pragma unroll
    for (int i = 0; i < 4; i++)
#pragma unroll
        for (int j = 0; j < 8; j++) acc[i][j] = 0ull;

    for (int k0 = 0; k0 < D; k0 += BK) {
#pragma unroll
        for (int p = 0; p < 2; p++) {
            int e  = tid + p * THREADS;
            int kk = e & (BK - 1);
            int m  = e >> 3;
            As[kk * ASTR + m] = features[(size_t)grow[m] * D + k0 + kk];
        }
#pragma unroll
        for (int p = 0; p < 2; p++) {
            int e  = tid + p * THREADS;
            int kk = e >> 6;
            int n4 = (e & 63) * 4;
            *(float4*)&Bs[kk * D + n4] = *(const float4*)&W[(size_t)(k0 + kk) * D + n4];
        }
        __syncthreads();
#pragma unroll
        for (int kk = 0; kk < BK; kk++) {
            ulonglong2 aP0 = *(ulonglong2*)&As[kk * ASTR + rg * 8];
            ulonglong2 aP1 = *(ulonglong2*)&As[kk * ASTR + rg * 8 + 4];
            unsigned long long a_[4] = {aP0.x, aP0.y, aP1.x, aP1.y};
            float4 b0 = *(float4*)&Bs[kk * D + cg * 4];
            float4 b1 = *(float4*)&Bs[kk * D + 128 + cg * 4];
            unsigned long long bb[8];
            bb[0] = pack2(b0.x); bb[1] = pack2(b0.y); bb[2] = pack2(b0.z); bb[3] = pack2(b0.w);
            bb[4] = pack2(b1.x); bb[5] = pack2(b1.y); bb[6] = pack2(b1.z); bb[7] = pack2(b1.w);
#pragma unroll
            for (int i2 = 0; i2 < 4; i2++)
#pragma unroll
                for (int j = 0; j < 8; j++)
                    fma2(acc[i2][j], a_[i2], bb[j]);
        }
        __syncthreads();
    }

    {
        float4 bias0 = *(const float4*)&bias[cg * 4];
        float4 bias1 = *(const float4*)&bias[128 + cg * 4];
        float bjs[8] = {bias0.x, bias0.y, bias0.z, bias0.w,
                        bias1.x, bias1.y, bias1.z, bias1.w};
#pragma unroll
        for (int i2 = 0; i2 < 4; i2++) {
            float lo[8], hi[8];
#pragma unroll
            for (int j = 0; j < 8; j++) {
                F2U u; u.u = acc[i2][j];
                lo[j] = u.f.x + bjs[j];
                hi[j] = u.f.y + bjs[j];
            }
            int r0 = rg * 8 + 2 * i2;
            *(float4*)&ls[r0 * D + cg * 4]        = make_float4(lo[0], lo[1], lo[2], lo[3]);
            *(float4*)&ls[r0 * D + 128 + cg * 4]  = make_float4(lo[4], lo[5], lo[6], lo[7]);
            *(float4*)&ls[(r0 + 1) * D + cg * 4]       = make_float4(hi[0], hi[1], hi[2], hi[3]);
            *(float4*)&ls[(r0 + 1) * D + 128 + cg * 4] = make_float4(hi[4], hi[5], hi[6], hi[7]);
        }
    }
    __syncthreads();

    // ---------------- Phase B: neighbor gather + dot + outputs ----------------
    // lane l accumulates P[s] = partial dot over dims [8l,8l+8) for ALL 32 samples,
    // then one recursive-halving butterfly (31 shfls) delivers O[s] to lane s.
    const int warp = tid >> 5;
    const int lane = tid & 31;
    const int myur = ur[lane];
    const size_t attOff = (size_t)VERT * S;
    const size_t nzOff  = (size_t)VERT * S * 2;
    const size_t mnOff  = nzOff + VERT;

    for (int t = 0; t < 8; t++) {
        const int v  = warp * 8 + t;
        const int gv = m0 + v;
        const int ga = grow[v];
        const int nb = adj_info[(size_t)ga * DEG + myur];  // lane's own sample id

        float4 l0 = *(float4*)&ls[v * D + lane * 8];
        float4 l1 = *(float4*)&ls[v * D + lane * 8 + 4];

        // 2-deep double-buffered prefetch (4 LDG.128 in flight per warp)
        int r0n = __shfl_sync(0xffffffffu, nb, 0);
        int r1n = __shfl_sync(0xffffffffu, nb, 1);
        const float4* q0 = (const float4*)&features[(size_t)r0n * D];
        const float4* q1 = (const float4*)&features[(size_t)r1n * D];
        float4 A0 = q0[2 * lane], B0 = q0[2 * lane + 1];
        float4 A1 = q1[2 * lane], B1 = q1[2 * lane + 1];

        float P[S];
#pragma unroll
        for (int s = 0; s < S; s++) {
            float4 ca = (s & 1) ? A1 : A0;
            float4 cb = (s & 1) ? B1 : B0;
            if (s + 2 < S) {
                int rn = __shfl_sync(0xffffffffu, nb, s + 2);
                const float4* qn = (const float4*)&features[(size_t)rn * D];
                if (s & 1) { A1 = qn[2 * lane]; B1 = qn[2 * lane + 1]; }
                else       { A0 = qn[2 * lane]; B0 = qn[2 * lane + 1]; }
            }
            float tacc;
            tacc = ca.x * l0.x;
            tacc = fmaf(ca.y, l0.y, tacc);
            tacc = fmaf(ca.z, l0.z, tacc);
            tacc = fmaf(ca.w, l0.w, tacc);
            tacc = fmaf(cb.x, l1.x, tacc);
            tacc = fmaf(cb.y, l1.y, tacc);
            tacc = fmaf(cb.z, l1.z, tacc);
            tacc = fmaf(cb.w, l1.w, tacc);
            P[s] = tacc;
        }

        // Butterfly transpose-reduce: after this, lane s holds O[s] in P[0].
#pragma unroll
        for (int off = 16; off >= 1; off >>= 1) {
#pragma unroll
            for (int i = 0; i < off; i++) {
                float send = (lane & off) ? P[i] : P[i + off];
                float recv = __shfl_xor_sync(0xffffffffu, send, off);
                P[i] = ((lane & off) ? P[i + off] : P[i]) + recv;
            }
        }
        float myout = fmaxf(P[0], 0.0f);

        float mean = myout;
#pragma unroll
        for (int off = 16; off; off >>= 1)
            mean += __shfl_xor_sync(0xffffffffu, mean, off);
        mean *= (1.0f / S);

        const bool cond = (nb == SENT) || (myout > 0.5f * mean);
        out[(size_t)gv * S + lane]          = (float)(cond ? SENT : nb);
        out[attOff + (size_t)gv * S + lane] = 1.0f;

        float nz = cond ? 0.0f : 1.0f;
#pragma unroll
        for (int off = 16; off; off >>= 1)
            nz += __shfl_xor_sync(0xffffffffu, nz, off);
        if (lane == 0) {
            out[nzOff + gv] = nz;
            out[mnOff + gv] = mean;
        }
    }
}

extern "C" void kernel_launch(void* const* d_in, const int* in_sizes, int n_in,
                              void* d_out, int out_size)
{
    (void)in_sizes; (void)n_in; (void)out_size;
    const int*   ids  = (const int*)d_in[0];
    const int*   urnd = (const int*)d_in[1];
    const int*   adj  = (const int*)d_in[2];
    const float* feat = (const float*)d_in[3];
    const float* W    = (const float*)d_in[4];
    const float* b    = (const float*)d_in[5];
    float*       out  = (float*)d_out;

    const size_t smem_bytes =
        (size_t)(TILE_M * D + BK * ASTR + BK * D) * sizeof(float) +
        (size_t)(TILE_M + S) * sizeof(int);

    cudaFuncSetAttribute(fused_sampler_kernel,
                         cudaFuncAttributeMaxDynamicSharedMemorySize,
                         (int)smem_bytes);

    fused_sampler_kernel<<<VERT / TILE_M, THREADS, smem_bytes>>>(
        ids, urnd, adj, feat, W, b, out);
}